// round 2
// baseline (speedup 1.0000x reference)
#include <cuda_runtime.h>
#include <stdint.h>

#define N_NODES 4096
#define NEMB 256
#define NOUT 128
#define QS 2048
#define NQ 256
#define NN 1024
#define TEMP 0.07f
#define NEG_INF (-9.0e15f)

// ---- output layout (flattened f32, reference tuple order) ----
#define OFF_LL   0L                                   // logits_local  [1024, 2049]
#define OFF_LABL (OFF_LL + (long)NN*(QS+1))           // labels_local  [1024]
#define OFF_LG   (OFF_LABL + NN)                      // logits_global [1024, 256]
#define OFF_LABG (OFF_LG + (long)NN*NQ)               // labels_global [1024]
#define OFF_NQ   (OFF_LABG + NN)                      // new_queue     [256,128,2048]
#define OFF_NIDS (OFF_NQ + (long)NQ*NOUT*QS)          // new_ids       [256,2048]
#define OFF_NPTR (OFF_NIDS + (long)NQ*QS)             // new_ptr       [256]

// ---- device scratch (no allocation allowed) ----
__device__ float g_wk1[NEMB*NEMB];
__device__ float g_bk1[NEMB];
__device__ float g_wk2[NEMB*NOUT];
__device__ float g_bk2[NOUT];
__device__ float g_q[NN*NOUT];
__device__ float g_k[NN*NOUT];
__device__ float g_negsum[NQ*NOUT];
__device__ float g_negmeanT[NOUT*NQ];
__device__ int   g_rank[NN];
__device__ int   g_cols[NN];
__device__ int   g_counts[NQ];
__device__ int   g_grp_off[NQ+1];
__device__ int   g_grp_items[NN];

// 1) momentum weight update + zero scratch accumulators
__global__ void k_momentum(const float* __restrict__ wq1, const float* __restrict__ bq1,
                           const float* __restrict__ wq2, const float* __restrict__ bq2,
                           const float* __restrict__ wk1, const float* __restrict__ bk1,
                           const float* __restrict__ wk2, const float* __restrict__ bk2) {
    int i = blockIdx.x*256 + threadIdx.x;
    if (i < 65536) { g_wk1[i] = wk1[i]*0.999f + wq1[i]*0.001f; return; }
    i -= 65536;
    if (i < 256)   { g_bk1[i] = bk1[i]*0.999f + bq1[i]*0.001f; return; }
    i -= 256;
    if (i < 32768) { g_wk2[i] = wk2[i]*0.999f + wq2[i]*0.001f; return; }
    i -= 32768;
    if (i < 128)   { g_bk2[i] = bk2[i]*0.999f + bq2[i]*0.001f; return; }
    i -= 128;
    if (i < 32768) { g_negsum[i] = 0.f; return; }
    i -= 32768;
    if (i < 256)   { g_counts[i] = 0; }
}

// 2) gather 16 rows -> MLP(relu) -> l2norm.  mom=0: q path, mom=1: k path.
__global__ void __launch_bounds__(256) k_proj(
        const float* __restrict__ X, const int* __restrict__ idx,
        const float* __restrict__ W1p, const float* __restrict__ B1p,
        const float* __restrict__ W2p, const float* __restrict__ B2p, int mom) {
    __shared__ float in_sh[16*256];
    __shared__ float h_sh [16*256];
    __shared__ float o_sh [16*128];
    __shared__ float nrm_sh[16];
    const float* W1 = mom ? g_wk1 : W1p;
    const float* B1 = mom ? g_bk1 : B1p;
    const float* W2 = mom ? g_wk2 : W2p;
    const float* B2 = mom ? g_bk2 : B2p;
    float* outQ = mom ? g_k : g_q;

    int tid = threadIdx.x;
    int n0  = blockIdx.x * 16;
    for (int t = tid; t < 16*256; t += 256) {
        int r = t >> 8, c = t & 255;
        in_sh[t] = X[(long)idx[n0+r]*NEMB + c];
    }
    __syncthreads();
    { // layer 1: 256 output cols, 16 rows per thread-col
        float acc[16];
        #pragma unroll
        for (int m=0;m<16;m++) acc[m]=0.f;
        for (int c4=0;c4<256;c4+=4) {
            float w0 = W1[(c4+0)*256+tid];
            float w1 = W1[(c4+1)*256+tid];
            float w2 = W1[(c4+2)*256+tid];
            float w3 = W1[(c4+3)*256+tid];
            #pragma unroll
            for (int m=0;m<16;m++) {
                float4 x = *(const float4*)&in_sh[m*256+c4];
                acc[m] += x.x*w0 + x.y*w1 + x.z*w2 + x.w*w3;
            }
        }
        float b = B1[tid];
        #pragma unroll
        for (int m=0;m<16;m++) h_sh[m*256+tid] = fmaxf(acc[m]+b, 0.f);
    }
    __syncthreads();
    { // layer 2: 128 output cols; thread -> (col = tid&127, row-half = tid>>7)
        int oc = tid & 127;
        int mb = (tid >> 7) * 8;
        float acc[8];
        #pragma unroll
        for (int m=0;m<8;m++) acc[m]=0.f;
        for (int c4=0;c4<256;c4+=4) {
            float w0 = W2[(c4+0)*128+oc];
            float w1 = W2[(c4+1)*128+oc];
            float w2 = W2[(c4+2)*128+oc];
            float w3 = W2[(c4+3)*128+oc];
            #pragma unroll
            for (int m=0;m<8;m++) {
                float4 x = *(const float4*)&h_sh[(mb+m)*256+c4];
                acc[m] += x.x*w0 + x.y*w1 + x.z*w2 + x.w*w3;
            }
        }
        float b = B2[oc];
        #pragma unroll
        for (int m=0;m<8;m++) o_sh[(mb+m)*128+oc] = acc[m]+b;
    }
    __syncthreads();
    if (tid < 16) {
        float ssq = 0.f;
        const float4* row = (const float4*)&o_sh[tid*128];
        #pragma unroll 8
        for (int i=0;i<32;i++) { float4 x=row[i]; ssq += x.x*x.x+x.y*x.y+x.z*x.z+x.w*x.w; }
        nrm_sh[tid] = 1.0f/sqrtf(ssq);
    }
    __syncthreads();
    for (int t=tid; t<16*128; t+=256) {
        int m = t>>7;
        outQ[(long)(n0+m)*NOUT + (t&127)] = o_sh[t]*nrm_sh[m];
    }
}

// 3) ranks/cols, l_pos, labels (8 blocks x 128)
__global__ void k_seq1(const int* __restrict__ q_ids, const int* __restrict__ queue_ptr,
                       float* __restrict__ out) {
    __shared__ int qid_sh[NN];
    int tid = threadIdx.x;
    int n = blockIdx.x*128 + tid;
    for (int t=tid; t<NN; t+=128) qid_sh[t] = q_ids[t];
    __syncthreads();
    int qid = qid_sh[n];
    int rank = 0;
    for (int i=0;i<n;i++) rank += (qid_sh[i]==qid);
    g_rank[n] = rank;
    g_cols[n] = (queue_ptr[qid] + rank) & (QS-1);
    atomicAdd(&g_counts[qid], 1);
    const float4* qa = (const float4*)(g_q + (long)n*NOUT);
    const float4* kb = (const float4*)(g_k + (long)n*NOUT);
    float d = 0.f;
    #pragma unroll 8
    for (int i=0;i<32;i++){ float4 a=qa[i], b=kb[i]; d += a.x*b.x+a.y*b.y+a.z*b.z+a.w*b.w; }
    out[OFF_LL + (long)n*(QS+1)] = d / TEMP;
    out[OFF_LABL + n] = 0.f;
    out[OFF_LABG + n] = (float)qid;
}

// 4) prefix-sum groups, new_ptr, group item scatter (1 block x 256)
__global__ void k_seq2(const int* __restrict__ q_ids, const int* __restrict__ queue_ptr,
                       float* __restrict__ out) {
    __shared__ int sc[NQ];
    __shared__ int excl[NQ];
    int tid = threadIdx.x;
    int c = g_counts[tid];
    sc[tid] = c;
    __syncthreads();
    for (int d=1; d<NQ; d<<=1) {
        int v = (tid>=d) ? sc[tid-d] : 0;
        __syncthreads();
        sc[tid] += v;
        __syncthreads();
    }
    int e = sc[tid]-c;
    excl[tid] = e;
    g_grp_off[tid] = e;
    if (tid==NQ-1) g_grp_off[NQ] = sc[NQ-1];
    out[OFF_NPTR + tid] = (float)((queue_ptr[tid]+c) & (QS-1));
    __syncthreads();
    for (int n=tid; n<NN; n+=NQ) {
        int qid = q_ids[n];
        g_grp_items[excl[qid] + g_rank[n]] = n;
    }
}

// 5) fused streaming pass over queue: copy -> new_queue, sum for mean,
//    grouped dots -> l_neg_local (+ mask), ids copy.  grid (4, 256) x 256.
//    Each block owns a 512-col slice of one queue id j.
__global__ void __launch_bounds__(256) k_main(const float* __restrict__ queue,
                       const int* __restrict__ ids, const int* __restrict__ elem_ids,
                       float* __restrict__ out) {
    __shared__ float qv_sh[8*128];
    __shared__ int   n_sh[8];
    __shared__ int   e_sh[8];
    __shared__ float wsum[8*128];
    int tid = threadIdx.x;
    int j   = blockIdx.y;
    int s0  = blockIdx.x * 512;
    const float* Qb = queue + (long)j*NOUT*QS + s0;
    float* NQo = out + OFF_NQ + (long)j*NOUT*QS + s0;

    // this block handles columns [s0, s0+512): 2 floats per thread per row? no:
    // 512 cols / 256 threads = 2 float2... use float2 per thread.
    float2 myid2;
    int2 myids = *(const int2*)(ids + (long)j*QS + s0 + tid*2);
    {
        float* dst = out + OFF_NIDS + (long)j*QS + s0 + tid*2;
        dst[0]=(float)myids.x; dst[1]=(float)myids.y;
        myid2.x = 0.f; myid2.y = 0.f; (void)myid2;
    }
    for (int t=tid; t<1024; t+=256) wsum[t]=0.f;

    int off = g_grp_off[j];
    int cnt = g_grp_off[j+1]-off;
    int nch = (cnt+7)>>3; if (nch==0) nch=1;

    for (int ch=0; ch<nch; ch++) {
        int cc = cnt - ch*8; if (cc>8) cc=8; if (cc<0) cc=0;
        __syncthreads();
        for (int t=tid; t<cc*128; t+=256) {
            int m = t>>7;
            int n = g_grp_items[off+ch*8+m];
            qv_sh[t] = g_q[(long)n*NOUT + (t&127)];
        }
        if (tid < cc) {
            int n = g_grp_items[off+ch*8+tid];
            n_sh[tid]=n; e_sh[tid]=elem_ids[n];
        }
        __syncthreads();
        float2 acc[8];
        #pragma unroll
        for (int m=0;m<8;m++) acc[m]=make_float2(0.f,0.f);
        for (int c=0;c<NOUT;c++) {
            float2 v = *(const float2*)(Qb + (long)c*QS + tid*2);
            if (ch==0) {
                *(float2*)(NQo + (long)c*QS + tid*2) = v;
                float p = v.x+v.y;
                p += __shfl_xor_sync(0xffffffffu, p, 16);
                p += __shfl_xor_sync(0xffffffffu, p, 8);
                p += __shfl_xor_sync(0xffffffffu, p, 4);
                p += __shfl_xor_sync(0xffffffffu, p, 2);
                p += __shfl_xor_sync(0xffffffffu, p, 1);
                if ((tid&31)==0) wsum[(tid>>5)*128 + c] += p;
            }
            #pragma unroll
            for (int m=0;m<8;m++) {
                if (m<cc) {
                    float qc = qv_sh[m*128+c];
                    acc[m].x += qc*v.x; acc[m].y += qc*v.y;
                }
            }
        }
        #pragma unroll
        for (int m=0;m<8;m++) {
            if (m<cc) {
                int n = n_sh[m], e = e_sh[m];
                float* dst = out + OFF_LL + (long)n*(QS+1) + 1 + s0 + tid*2;
                dst[0] = (myids.x==e) ? (NEG_INF/TEMP) : acc[m].x/TEMP;
                dst[1] = (myids.y==e) ? (NEG_INF/TEMP) : acc[m].y/TEMP;
            }
        }
    }
    __syncthreads();
    if (tid < 128) {
        float s = 0.f;
        #pragma unroll
        for (int w=0;w<8;w++) s += wsum[w*128+tid];
        atomicAdd(&g_negsum[(long)j*128+tid], s);
    }
}

// 6) transpose + scale the mean
__global__ void k_negmean() {
    int i = blockIdx.x*256+threadIdx.x;   // 32768
    int j = i & 255, c = i >> 8;
    g_negmeanT[c*NQ + j] = g_negsum[j*NOUT + c] * (1.0f/2048.0f);
}

// 7) logits_global = q @ neg_global^T / TEMP  (64 blocks x 256)
__global__ void __launch_bounds__(256) k_global(float* __restrict__ out) {
    __shared__ float q_sh[16*128];
    int tid = threadIdx.x;
    int n0 = blockIdx.x*16;
    for (int t=tid; t<2048; t+=256) q_sh[t] = g_q[(long)n0*128 + t];
    __syncthreads();
    int jq = tid;
    float acc[16];
    #pragma unroll
    for (int m=0;m<16;m++) acc[m]=0.f;
    for (int c4=0;c4<128;c4+=4) {
        float w0 = g_negmeanT[(c4+0)*NQ+jq];
        float w1 = g_negmeanT[(c4+1)*NQ+jq];
        float w2 = g_negmeanT[(c4+2)*NQ+jq];
        float w3 = g_negmeanT[(c4+3)*NQ+jq];
        #pragma unroll
        for (int m=0;m<16;m++) {
            float4 x = *(const float4*)&q_sh[m*128+c4];
            acc[m] += x.x*w0+x.y*w1+x.z*w2+x.w*w3;
        }
    }
    #pragma unroll
    for (int m=0;m<16;m++)
        out[OFF_LG + (long)(n0+m)*NQ + jq] = acc[m]/TEMP;
}

// 8) enqueue scatter of k-vectors and elem_ids (after bulk copy)
__global__ void k_scatter(const int* __restrict__ q_ids, const int* __restrict__ elem_ids,
                          float* __restrict__ out) {
    int n = blockIdx.x;
    int tid = threadIdx.x;
    int col = g_cols[n];
    int qid = q_ids[n];
    out[OFF_NQ + (long)qid*NOUT*QS + (long)tid*QS + col] = g_k[(long)n*NOUT+tid];
    if (tid==0) out[OFF_NIDS + (long)qid*QS + col] = (float)elem_ids[n];
}

extern "C" void kernel_launch(void* const* d_in, const int* in_sizes, int n_in,
                              void* d_out, int out_size) {
    (void)in_sizes; (void)n_in; (void)out_size;
    const float* inputs_q  = (const float*)d_in[0];
    const float* inputs_k  = (const float*)d_in[1];
    const int*   idx_q     = (const int*)d_in[2];
    const int*   idx_k     = (const int*)d_in[3];
    const int*   q_ids     = (const int*)d_in[4];
    const int*   elem_ids  = (const int*)d_in[5];
    const float* wq1 = (const float*)d_in[6];
    const float* bq1 = (const float*)d_in[7];
    const float* wq2 = (const float*)d_in[8];
    const float* bq2 = (const float*)d_in[9];
    const float* wk1 = (const float*)d_in[10];
    const float* bk1 = (const float*)d_in[11];
    const float* wk2 = (const float*)d_in[12];
    const float* bk2 = (const float*)d_in[13];
    const float* queue     = (const float*)d_in[14];
    const int*   ids       = (const int*)d_in[15];
    const int*   queue_ptr = (const int*)d_in[16];
    float* out = (float*)d_out;

    k_momentum<<<515,256>>>(wq1,bq1,wq2,bq2,wk1,bk1,wk2,bk2);
    k_proj<<<64,256>>>(inputs_q, idx_q, wq1,bq1,wq2,bq2, 0);
    k_proj<<<64,256>>>(inputs_k, idx_k, wq1,bq1,wq2,bq2, 1); // uses g_wk* internally
    k_seq1<<<8,128>>>(q_ids, queue_ptr, out);
    k_seq2<<<1,256>>>(q_ids, queue_ptr, out);
    dim3 gmain(4,256);
    k_main<<<gmain,256>>>(queue, ids, elem_ids, out);
    k_negmean<<<128,256>>>();
    k_global<<<64,256>>>(out);
    k_scatter<<<1024,128>>>(q_ids, elem_ids, out);
}

// round 4
// speedup vs baseline: 1.5234x; 1.5234x over previous
#include <cuda_runtime.h>
#include <stdint.h>

#define N_NODES 4096
#define NEMB 256
#define NOUT 128
#define QS 2048
#define NQ 256
#define NN 1024
#define TEMP 0.07f
#define NEG_INF (-9.0e15f)

// ---- output layout (flattened f32, reference tuple order) ----
#define OFF_LL   0L                                   // logits_local  [1024, 2049]
#define OFF_LABL (OFF_LL + (long)NN*(QS+1))           // labels_local  [1024]
#define OFF_LG   (OFF_LABL + NN)                      // logits_global [1024, 256]
#define OFF_LABG (OFF_LG + (long)NN*NQ)               // labels_global [1024]
#define OFF_NQ   (OFF_LABG + NN)                      // new_queue     [256,128,2048]
#define OFF_NIDS (OFF_NQ + (long)NQ*NOUT*QS)          // new_ids       [256,2048]
#define OFF_NPTR (OFF_NIDS + (long)NQ*QS)             // new_ptr       [256]

// ---- device scratch (no allocation allowed; every element fully
//      overwritten on every call => replay-deterministic) ----
__device__ float g_wk1[NEMB*NEMB];
__device__ float g_bk1[NEMB];
__device__ float g_wk2[NEMB*NOUT];
__device__ float g_bk2[NOUT];
__device__ float g_q[NN*NOUT];
__device__ float g_k[NN*NOUT];
__device__ float g_negpart[2*NQ*NOUT];   // per-(s-half) partial column sums
__device__ float g_negmeanT[NOUT*NQ];
__device__ int   g_rank[NN];
__device__ int   g_cols[NN];
__device__ int   g_counts[NQ];
__device__ int   g_grp_off[NQ+1];
__device__ int   g_grp_items[NN];

// 1) momentum weight update (98688 items; 386 blocks x 256)
__global__ void k_momentum(const float* __restrict__ wq1, const float* __restrict__ bq1,
                           const float* __restrict__ wq2, const float* __restrict__ bq2,
                           const float* __restrict__ wk1, const float* __restrict__ bk1,
                           const float* __restrict__ wk2, const float* __restrict__ bk2) {
    int i = blockIdx.x*256 + threadIdx.x;
    if (i < 65536) { g_wk1[i] = wk1[i]*0.999f + wq1[i]*0.001f; return; }
    i -= 65536;
    if (i < 256)   { g_bk1[i] = bk1[i]*0.999f + bq1[i]*0.001f; return; }
    i -= 256;
    if (i < 32768) { g_wk2[i] = wk2[i]*0.999f + wq2[i]*0.001f; return; }
    i -= 32768;
    if (i < 128)   { g_bk2[i] = bk2[i]*0.999f + bq2[i]*0.001f; }
}

// 2) merged q/k projection: blocks [0,64) -> q path, [64,128) -> k path.
__global__ void __launch_bounds__(256) k_proj2(
        const float* __restrict__ Xq, const float* __restrict__ Xk,
        const int* __restrict__ idxq, const int* __restrict__ idxk,
        const float* __restrict__ W1p, const float* __restrict__ B1p,
        const float* __restrict__ W2p, const float* __restrict__ B2p) {
    __shared__ float in_sh[16*256];
    __shared__ float h_sh [16*256];
    __shared__ float o_sh [16*128];
    __shared__ float nrm_sh[16];
    int mom = blockIdx.x >= 64;
    int blk = blockIdx.x & 63;
    const float* X   = mom ? Xk : Xq;
    const int*   idx = mom ? idxk : idxq;
    const float* W1  = mom ? g_wk1 : W1p;
    const float* B1  = mom ? g_bk1 : B1p;
    const float* W2  = mom ? g_wk2 : W2p;
    const float* B2  = mom ? g_bk2 : B2p;
    float* outQ = mom ? g_k : g_q;

    int tid = threadIdx.x;
    int n0  = blk * 16;
    for (int t = tid; t < 16*256; t += 256) {
        int r = t >> 8, c = t & 255;
        in_sh[t] = X[(long)idx[n0+r]*NEMB + c];
    }
    __syncthreads();
    { // layer 1
        float acc[16];
        #pragma unroll
        for (int m=0;m<16;m++) acc[m]=0.f;
        for (int c4=0;c4<256;c4+=4) {
            float w0 = W1[(c4+0)*256+tid];
            float w1 = W1[(c4+1)*256+tid];
            float w2 = W1[(c4+2)*256+tid];
            float w3 = W1[(c4+3)*256+tid];
            #pragma unroll
            for (int m=0;m<16;m++) {
                float4 x = *(const float4*)&in_sh[m*256+c4];
                acc[m] += x.x*w0 + x.y*w1 + x.z*w2 + x.w*w3;
            }
        }
        float b = B1[tid];
        #pragma unroll
        for (int m=0;m<16;m++) h_sh[m*256+tid] = fmaxf(acc[m]+b, 0.f);
    }
    __syncthreads();
    { // layer 2
        int oc = tid & 127;
        int mb = (tid >> 7) * 8;
        float acc[8];
        #pragma unroll
        for (int m=0;m<8;m++) acc[m]=0.f;
        for (int c4=0;c4<256;c4+=4) {
            float w0 = W2[(c4+0)*128+oc];
            float w1 = W2[(c4+1)*128+oc];
            float w2 = W2[(c4+2)*128+oc];
            float w3 = W2[(c4+3)*128+oc];
            #pragma unroll
            for (int m=0;m<8;m++) {
                float4 x = *(const float4*)&h_sh[(mb+m)*256+c4];
                acc[m] += x.x*w0 + x.y*w1 + x.z*w2 + x.w*w3;
            }
        }
        float b = B2[oc];
        #pragma unroll
        for (int m=0;m<8;m++) o_sh[(mb+m)*128+oc] = acc[m]+b;
    }
    __syncthreads();
    if (tid < 16) {
        float ssq = 0.f;
        const float4* row = (const float4*)&o_sh[tid*128];
        #pragma unroll 8
        for (int i=0;i<32;i++) { float4 x=row[i]; ssq += x.x*x.x+x.y*x.y+x.z*x.z+x.w*x.w; }
        nrm_sh[tid] = 1.0f/sqrtf(ssq);
    }
    __syncthreads();
    for (int t=tid; t<16*128; t+=256) {
        int m = t>>7;
        outQ[(long)(n0+m)*NOUT + (t&127)] = o_sh[t]*nrm_sh[m];
    }
}

// 3) ranks/cols/counts via match_any + per-warp histograms. 1 block x 1024.
__global__ void __launch_bounds__(1024) k_rank(const int* __restrict__ q_ids,
                                               const int* __restrict__ queue_ptr) {
    __shared__ int hist[32*NQ];   // 32 KB
    int tid = threadIdx.x;
    int warp = tid >> 5, lane = tid & 31;
    for (int t=tid; t<32*NQ; t+=1024) hist[t]=0;
    __syncthreads();
    int qid = q_ids[tid];
    unsigned m = __match_any_sync(0xffffffffu, qid);
    int intra = __popc(m & ((1u<<lane)-1u));
    int leader = __ffs(m)-1;
    if (lane==leader) hist[warp*NQ + qid] = __popc(m);
    __syncthreads();
    int prior=0;
    #pragma unroll 4
    for (int w=0; w<warp; w++) prior += hist[w*NQ+qid];
    int rank = prior + intra;
    g_rank[tid] = rank;
    g_cols[tid] = (queue_ptr[qid] + rank) & (QS-1);
    if (tid < NQ) {
        int c=0;
        #pragma unroll 8
        for (int w=0;w<32;w++) c += hist[w*NQ+tid];
        g_counts[tid]=c;
    }
}

// 4) l_pos + labels: warp per row. grid 128 x 256.
__global__ void k_lpos(const int* __restrict__ q_ids, float* __restrict__ out) {
    int warp = threadIdx.x>>5, lane = threadIdx.x&31;
    int n = blockIdx.x*8 + warp;
    float4 a = *(const float4*)(g_q + (long)n*NOUT + lane*4);
    float4 b = *(const float4*)(g_k + (long)n*NOUT + lane*4);
    float d = a.x*b.x + a.y*b.y + a.z*b.z + a.w*b.w;
    #pragma unroll
    for (int o=16;o;o>>=1) d += __shfl_xor_sync(0xffffffffu, d, o);
    if (lane==0) {
        out[OFF_LL + (long)n*(QS+1)] = d / TEMP;
        out[OFF_LABL + n] = 0.f;
        out[OFF_LABG + n] = (float)q_ids[n];
    }
}

// 5) prefix-sum groups, new_ptr, group item scatter (1 block x 256)
__global__ void k_seq2(const int* __restrict__ q_ids, const int* __restrict__ queue_ptr,
                       float* __restrict__ out) {
    __shared__ int sc[NQ];
    __shared__ int excl[NQ];
    int tid = threadIdx.x;
    int c = g_counts[tid];
    sc[tid] = c;
    __syncthreads();
    for (int d=1; d<NQ; d<<=1) {
        int v = (tid>=d) ? sc[tid-d] : 0;
        __syncthreads();
        sc[tid] += v;
        __syncthreads();
    }
    int e = sc[tid]-c;
    excl[tid] = e;
    g_grp_off[tid] = e;
    if (tid==NQ-1) g_grp_off[NQ] = sc[NQ-1];
    out[OFF_NPTR + tid] = (float)((queue_ptr[tid]+c) & (QS-1));
    __syncthreads();
    for (int n=tid; n<NN; n+=NQ) {
        int qid = q_ids[n];
        g_grp_items[excl[qid] + g_rank[n]] = n;
    }
}

// 6) fused streaming pass: copy queue->new_queue, column sums, grouped dots,
//    ids copy, and enqueue scatter (block owns its (j, s-half) exclusively).
//    grid (2, 256) x 256 threads; float4 per lane.
template<int CC, bool COPY>
__device__ __forceinline__ void chunk_body(
        const float* __restrict__ Qb, float* __restrict__ NQo,
        float* __restrict__ wsum, const float* __restrict__ qv_sh,
        int tid, float4* acc) {
    for (int c=0;c<NOUT;c+=2) {
        float4 v0 = *(const float4*)(Qb + (long)c*QS);
        float4 v1 = *(const float4*)(Qb + (long)(c+1)*QS);
        if (COPY) {
            *(float4*)(NQo + (long)c*QS)     = v0;
            *(float4*)(NQo + (long)(c+1)*QS) = v1;
            float p0 = v0.x+v0.y+v0.z+v0.w;
            float p1 = v1.x+v1.y+v1.z+v1.w;
            #pragma unroll
            for (int o=16;o;o>>=1) {
                p0 += __shfl_xor_sync(0xffffffffu, p0, o);
                p1 += __shfl_xor_sync(0xffffffffu, p1, o);
            }
            if ((tid&31)==0) {
                wsum[(tid>>5)*NOUT + c]   += p0;
                wsum[(tid>>5)*NOUT + c+1] += p1;
            }
        }
        if (CC > 0) {
            const float4* q0p = (const float4*)(qv_sh + c*8);
            const float4* q1p = (const float4*)(qv_sh + (c+1)*8);
            float4 qa0 = q0p[0], qb0 = q0p[1];
            float4 qa1 = q1p[0], qb1 = q1p[1];
            float qm0[8] = {qa0.x,qa0.y,qa0.z,qa0.w,qb0.x,qb0.y,qb0.z,qb0.w};
            float qm1[8] = {qa1.x,qa1.y,qa1.z,qa1.w,qb1.x,qb1.y,qb1.z,qb1.w};
            #pragma unroll
            for (int m=0;m<CC;m++) {
                acc[m].x += qm0[m]*v0.x + qm1[m]*v1.x;
                acc[m].y += qm0[m]*v0.y + qm1[m]*v1.y;
                acc[m].z += qm0[m]*v0.z + qm1[m]*v1.z;
                acc[m].w += qm0[m]*v0.w + qm1[m]*v1.w;
            }
        }
    }
}

__global__ void __launch_bounds__(256) k_main(const float* __restrict__ queue,
                       const int* __restrict__ ids, const int* __restrict__ elem_ids,
                       float* __restrict__ out) {
    __shared__ float qv_sh[NOUT*8];   // [c][m] layout
    __shared__ int   n_sh[8];
    __shared__ int   e_sh[8];
    __shared__ float wsum[8*NOUT];
    int tid = threadIdx.x;
    int j   = blockIdx.y;
    int s0  = blockIdx.x * 1024;
    const float* Qb = queue + (long)j*NOUT*QS + s0 + tid*4;
    float* NQo = out + OFF_NQ + (long)j*NOUT*QS + s0 + tid*4;

    int4 myids = *(const int4*)(ids + (long)j*QS + s0 + tid*4);
    {
        float* dst = out + OFF_NIDS + (long)j*QS + s0 + tid*4;
        dst[0]=(float)myids.x; dst[1]=(float)myids.y;
        dst[2]=(float)myids.z; dst[3]=(float)myids.w;
    }
    for (int t=tid; t<8*NOUT; t+=256) wsum[t]=0.f;

    int off = g_grp_off[j];
    int cnt = g_grp_off[j+1]-off;
    int nch = (cnt+7)>>3; if (nch==0) nch=1;

    for (int ch=0; ch<nch; ch++) {
        int cc = cnt - ch*8; if (cc>8) cc=8; if (cc<0) cc=0;
        __syncthreads();
        for (int t=tid; t<NOUT*8; t+=256) {
            int m = t & 7;
            if (m < cc)
                qv_sh[t] = g_q[(long)g_grp_items[off+ch*8+m]*NOUT + (t>>3)];
        }
        if (tid < cc) {
            int n = g_grp_items[off+ch*8+tid];
            n_sh[tid]=n; e_sh[tid]=elem_ids[n];
        }
        __syncthreads();

        float4 acc[8];
        #pragma unroll
        for (int m=0;m<8;m++) acc[m]=make_float4(0.f,0.f,0.f,0.f);

        bool copy = (ch==0);
        #define DISP(CCV) case CCV: \
            if (copy) chunk_body<CCV,true >(Qb,NQo,wsum,qv_sh,tid,acc); \
            else      chunk_body<CCV,false>(Qb,NQo,wsum,qv_sh,tid,acc); break;
        switch (cc) {
            DISP(0) DISP(1) DISP(2) DISP(3) DISP(4) DISP(5) DISP(6) DISP(7) DISP(8)
        }
        #undef DISP

        for (int m=0;m<cc;m++) {
            int n = n_sh[m], e = e_sh[m];
            float* dst = out + OFF_LL + (long)n*(QS+1) + 1 + s0 + tid*4;
            dst[0] = (myids.x==e) ? (NEG_INF/TEMP) : acc[m].x/TEMP;
            dst[1] = (myids.y==e) ? (NEG_INF/TEMP) : acc[m].y/TEMP;
            dst[2] = (myids.z==e) ? (NEG_INF/TEMP) : acc[m].z/TEMP;
            dst[3] = (myids.w==e) ? (NEG_INF/TEMP) : acc[m].w/TEMP;
        }
    }
    __syncthreads();
    // per-(s-half) partial column sums: plain store into a private slot.
    if (tid < 128) {
        float s = 0.f;
        #pragma unroll
        for (int w=0;w<8;w++) s += wsum[w*NOUT+tid];
        g_negpart[((long)blockIdx.x*NQ + j)*NOUT + tid] = s;
    }
    // enqueue overwrite: this block exclusively owns (j, [s0, s0+1024))
    if (tid < 128) {
        for (int i=0;i<cnt;i++) {
            int n = g_grp_items[off+i];
            int col = g_cols[n];
            if (col >= s0 && col < s0+1024) {
                out[OFF_NQ + (long)j*NOUT*QS + (long)tid*QS + col] = g_k[(long)n*NOUT+tid];
                if (tid==0) out[OFF_NIDS + (long)j*QS + col] = (float)elem_ids[n];
            }
        }
    }
}

// 7) combine partials, transpose + scale the mean
__global__ void k_negmean() {
    int i = blockIdx.x*256+threadIdx.x;   // 32768
    int j = i >> 7, c = i & 127;
    float s = g_negpart[(long)j*NOUT+c] + g_negpart[(long)(NQ+j)*NOUT+c];
    g_negmeanT[c*NQ + j] = s * (1.0f/2048.0f);
}

// 8) logits_global = q @ neg_global^T / TEMP  (64 blocks x 256)
__global__ void __launch_bounds__(256) k_global(float* __restrict__ out) {
    __shared__ float q_sh[16*128];
    int tid = threadIdx.x;
    int n0 = blockIdx.x*16;
    for (int t=tid; t<2048; t+=256) q_sh[t] = g_q[(long)n0*128 + t];
    __syncthreads();
    int jq = tid;
    float acc[16];
    #pragma unroll
    for (int m=0;m<16;m++) acc[m]=0.f;
    for (int c4=0;c4<128;c4+=4) {
        float w0 = g_negmeanT[(c4+0)*NQ+jq];
        float w1 = g_negmeanT[(c4+1)*NQ+jq];
        float w2 = g_negmeanT[(c4+2)*NQ+jq];
        float w3 = g_negmeanT[(c4+3)*NQ+jq];
        #pragma unroll
        for (int m=0;m<16;m++) {
            float4 x = *(const float4*)&q_sh[m*128+c4];
            acc[m] += x.x*w0+x.y*w1+x.z*w2+x.w*w3;
        }
    }
    #pragma unroll
    for (int m=0;m<16;m++)
        out[OFF_LG + (long)(n0+m)*NQ + jq] = acc[m]/TEMP;
}

extern "C" void kernel_launch(void* const* d_in, const int* in_sizes, int n_in,
                              void* d_out, int out_size) {
    (void)in_sizes; (void)n_in; (void)out_size;
    const float* inputs_q  = (const float*)d_in[0];
    const float* inputs_k  = (const float*)d_in[1];
    const int*   idx_q     = (const int*)d_in[2];
    const int*   idx_k     = (const int*)d_in[3];
    const int*   q_ids     = (const int*)d_in[4];
    const int*   elem_ids  = (const int*)d_in[5];
    const float* wq1 = (const float*)d_in[6];
    const float* bq1 = (const float*)d_in[7];
    const float* wq2 = (const float*)d_in[8];
    const float* bq2 = (const float*)d_in[9];
    const float* wk1 = (const float*)d_in[10];
    const float* bk1 = (const float*)d_in[11];
    const float* wk2 = (const float*)d_in[12];
    const float* bk2 = (const float*)d_in[13];
    const float* queue     = (const float*)d_in[14];
    const int*   ids       = (const int*)d_in[15];
    const int*   queue_ptr = (const int*)d_in[16];
    float* out = (float*)d_out;

    k_momentum<<<386,256>>>(wq1,bq1,wq2,bq2,wk1,bk1,wk2,bk2);
    k_proj2<<<128,256>>>(inputs_q, inputs_k, idx_q, idx_k, wq1,bq1,wq2,bq2);
    k_rank<<<1,1024>>>(q_ids, queue_ptr);
    k_lpos<<<128,256>>>(q_ids, out);
    k_seq2<<<1,256>>>(q_ids, queue_ptr, out);
    dim3 gmain(2,256);
    k_main<<<gmain,256>>>(queue, ids, elem_ids, out);
    k_negmean<<<128,256>>>();
    k_global<<<64,256>>>(out);
}

// round 5
// speedup vs baseline: 1.7365x; 1.1399x over previous
#include <cuda_runtime.h>
#include <stdint.h>

#define N_NODES 4096
#define NEMB 256
#define NOUT 128
#define QS 2048
#define NQ 256
#define NN 1024
#define TEMP 0.07f
#define NEG_INF (-9.0e15f)

// ---- output layout (flattened f32, reference tuple order) ----
#define OFF_LL   0L                                   // logits_local  [1024, 2049]
#define OFF_LABL (OFF_LL + (long)NN*(QS+1))           // labels_local  [1024]
#define OFF_LG   (OFF_LABL + NN)                      // logits_global [1024, 256]
#define OFF_LABG (OFF_LG + (long)NN*NQ)               // labels_global [1024]
#define OFF_NQ   (OFF_LABG + NN)                      // new_queue     [256,128,2048]
#define OFF_NIDS (OFF_NQ + (long)NQ*NOUT*QS)          // new_ids       [256,2048]
#define OFF_NPTR (OFF_NIDS + (long)NQ*QS)             // new_ptr       [256]

// ---- device scratch (every element fully overwritten every call) ----
__device__ float g_wk1[NEMB*NEMB];
__device__ float g_bk1[NEMB];
__device__ float g_wk2[NEMB*NOUT];
__device__ float g_bk2[NOUT];
__device__ float g_q[NN*NOUT];
__device__ float g_k[NN*NOUT];
__device__ float g_negpart[4*NQ*NOUT];   // per-s-quarter partial column sums
__device__ float g_negmeanT[NOUT*NQ];
__device__ int   g_cols[NN];
__device__ int   g_grp_off[NQ+1];
__device__ int   g_grp_items[NN];

// 1) momentum weight update (98688 items; 386 blocks x 256)
__global__ void k_momentum(const float* __restrict__ wq1, const float* __restrict__ bq1,
                           const float* __restrict__ wq2, const float* __restrict__ bq2,
                           const float* __restrict__ wk1, const float* __restrict__ bk1,
                           const float* __restrict__ wk2, const float* __restrict__ bk2) {
    int i = blockIdx.x*256 + threadIdx.x;
    if (i < 65536) { g_wk1[i] = wk1[i]*0.999f + wq1[i]*0.001f; return; }
    i -= 65536;
    if (i < 256)   { g_bk1[i] = bk1[i]*0.999f + bq1[i]*0.001f; return; }
    i -= 256;
    if (i < 32768) { g_wk2[i] = wk2[i]*0.999f + wq2[i]*0.001f; return; }
    i -= 32768;
    if (i < 128)   { g_bk2[i] = bk2[i]*0.999f + bq2[i]*0.001f; }
}

// 2) merged q/k projection: blocks [0,64) -> q path, [64,128) -> k path.
__global__ void __launch_bounds__(256) k_proj2(
        const float* __restrict__ Xq, const float* __restrict__ Xk,
        const int* __restrict__ idxq, const int* __restrict__ idxk,
        const float* __restrict__ W1p, const float* __restrict__ B1p,
        const float* __restrict__ W2p, const float* __restrict__ B2p) {
    __shared__ float in_sh[16*256];
    __shared__ float h_sh [16*256];
    __shared__ float o_sh [16*128];
    __shared__ float nrm_sh[16];
    int mom = blockIdx.x >= 64;
    int blk = blockIdx.x & 63;
    const float* X   = mom ? Xk : Xq;
    const int*   idx = mom ? idxk : idxq;
    const float* W1  = mom ? g_wk1 : W1p;
    const float* B1  = mom ? g_bk1 : B1p;
    const float* W2  = mom ? g_wk2 : W2p;
    const float* B2  = mom ? g_bk2 : B2p;
    float* outQ = mom ? g_k : g_q;

    int tid = threadIdx.x;
    int n0  = blk * 16;
    for (int t = tid; t < 16*256; t += 256) {
        int r = t >> 8, c = t & 255;
        in_sh[t] = X[(long)idx[n0+r]*NEMB + c];
    }
    __syncthreads();
    { // layer 1
        float acc[16];
        #pragma unroll
        for (int m=0;m<16;m++) acc[m]=0.f;
        for (int c4=0;c4<256;c4+=4) {
            float w0 = W1[(c4+0)*256+tid];
            float w1 = W1[(c4+1)*256+tid];
            float w2 = W1[(c4+2)*256+tid];
            float w3 = W1[(c4+3)*256+tid];
            #pragma unroll
            for (int m=0;m<16;m++) {
                float4 x = *(const float4*)&in_sh[m*256+c4];
                acc[m] += x.x*w0 + x.y*w1 + x.z*w2 + x.w*w3;
            }
        }
        float b = B1[tid];
        #pragma unroll
        for (int m=0;m<16;m++) h_sh[m*256+tid] = fmaxf(acc[m]+b, 0.f);
    }
    __syncthreads();
    { // layer 2
        int oc = tid & 127;
        int mb = (tid >> 7) * 8;
        float acc[8];
        #pragma unroll
        for (int m=0;m<8;m++) acc[m]=0.f;
        for (int c4=0;c4<256;c4+=4) {
            float w0 = W2[(c4+0)*128+oc];
            float w1 = W2[(c4+1)*128+oc];
            float w2 = W2[(c4+2)*128+oc];
            float w3 = W2[(c4+3)*128+oc];
            #pragma unroll
            for (int m=0;m<8;m++) {
                float4 x = *(const float4*)&h_sh[(mb+m)*256+c4];
                acc[m] += x.x*w0 + x.y*w1 + x.z*w2 + x.w*w3;
            }
        }
        float b = B2[oc];
        #pragma unroll
        for (int m=0;m<8;m++) o_sh[(mb+m)*128+oc] = acc[m]+b;
    }
    __syncthreads();
    if (tid < 16) {
        float ssq = 0.f;
        const float4* row = (const float4*)&o_sh[tid*128];
        #pragma unroll 8
        for (int i=0;i<32;i++) { float4 x=row[i]; ssq += x.x*x.x+x.y*x.y+x.z*x.z+x.w*x.w; }
        nrm_sh[tid] = 1.0f/sqrtf(ssq);
    }
    __syncthreads();
    for (int t=tid; t<16*128; t+=256) {
        int m = t>>7;
        outQ[(long)(n0+m)*NOUT + (t&127)] = o_sh[t]*nrm_sh[m];
    }
}

// 3) fused metadata kernel: ranks/cols/counts (match_any), prefix-scan groups,
//    new_ptr, group item scatter, l_pos + labels.  1 block x 1024 threads.
__global__ void __launch_bounds__(1024) k_meta(const int* __restrict__ q_ids,
                                               const int* __restrict__ queue_ptr,
                                               float* __restrict__ out) {
    __shared__ int hist[32*NQ];   // 32 KB
    __shared__ int sc[NQ];
    __shared__ int excl[NQ];
    __shared__ int cnt_sh[NQ];
    int tid = threadIdx.x;
    int warp = tid >> 5, lane = tid & 31;
    for (int t=tid; t<32*NQ; t+=1024) hist[t]=0;
    __syncthreads();
    int qid = q_ids[tid];
    unsigned m = __match_any_sync(0xffffffffu, qid);
    int intra = __popc(m & ((1u<<lane)-1u));
    int leader = __ffs(m)-1;
    if (lane==leader) hist[warp*NQ + qid] = __popc(m);
    __syncthreads();
    int prior=0;
    #pragma unroll 4
    for (int w=0; w<warp; w++) prior += hist[w*NQ+qid];
    int rank = prior + intra;
    g_cols[tid] = (queue_ptr[qid] + rank) & (QS-1);
    if (tid < NQ) {
        int c=0;
        #pragma unroll 8
        for (int w=0;w<32;w++) c += hist[w*NQ+tid];
        cnt_sh[tid]=c;
        sc[tid]=c;
    }
    __syncthreads();
    // inclusive scan over NQ (all threads hit barriers)
    for (int d=1; d<NQ; d<<=1) {
        int v = 0;
        if (tid < NQ && tid >= d) v = sc[tid-d];
        __syncthreads();
        if (tid < NQ) sc[tid] += v;
        __syncthreads();
    }
    if (tid < NQ) {
        int c = cnt_sh[tid];
        int e = sc[tid]-c;
        excl[tid] = e;
        g_grp_off[tid] = e;
        if (tid==NQ-1) g_grp_off[NQ] = sc[NQ-1];
        out[OFF_NPTR + tid] = (float)((queue_ptr[tid]+c) & (QS-1));
    }
    __syncthreads();
    g_grp_items[excl[qid] + rank] = tid;

    // l_pos + labels: warp per row, 32 rows per warp
    for (int n = warp; n < NN; n += 32) {
        float4 a = *(const float4*)(g_q + (long)n*NOUT + lane*4);
        float4 b = *(const float4*)(g_k + (long)n*NOUT + lane*4);
        float d = a.x*b.x + a.y*b.y + a.z*b.z + a.w*b.w;
        #pragma unroll
        for (int o=16;o;o>>=1) d += __shfl_xor_sync(0xffffffffu, d, o);
        if (lane==0) {
            out[OFF_LL + (long)n*(QS+1)] = d / TEMP;
            out[OFF_LABL + n] = 0.f;
            out[OFF_LABG + n] = (float)q_ids[n];
        }
    }
}

// 4) fused streaming pass: copy queue->new_queue, column sums, grouped dots,
//    ids copy, enqueue scatter.  grid (4, 256) x 128 threads; block owns the
//    s-slice [s0, s0+512) of queue id j exclusively.
template<int CC, bool COPY>
__device__ __forceinline__ void run_cols(
        const float* __restrict__ Qb, float* __restrict__ NQo,
        float* __restrict__ wsumW, const float* __restrict__ qv_sh,
        int lane, float4* acc) {
    float4 cur[4];
    #pragma unroll
    for (int u=0;u<4;u++) cur[u] = __ldcs((const float4*)(Qb + (long)u*QS));
    #pragma unroll
    for (int c0=0;c0<NOUT;c0+=4) {
        float4 nxt[4];
        if (c0+4 < NOUT) {
            #pragma unroll
            for (int u=0;u<4;u++)
                nxt[u] = __ldcs((const float4*)(Qb + (long)(c0+4+u)*QS));
        }
        if (COPY) {
            float p[4];
            #pragma unroll
            for (int u=0;u<4;u++) {
                __stcs((float4*)(NQo + (long)(c0+u)*QS), cur[u]);
                p[u] = (cur[u].x+cur[u].y)+(cur[u].z+cur[u].w);
            }
            #pragma unroll
            for (int o=16;o;o>>=1) {
                #pragma unroll
                for (int u=0;u<4;u++) p[u] += __shfl_xor_sync(0xffffffffu, p[u], o);
            }
            if (lane==0) {
                #pragma unroll
                for (int u=0;u<4;u++) wsumW[c0+u] += p[u];
            }
        }
        if (CC > 0) {
            #pragma unroll
            for (int u=0;u<4;u++) {
                const float4* qp = (const float4*)(qv_sh + (c0+u)*8);
                float4 qa = qp[0], qb = qp[1];
                float qm[8] = {qa.x,qa.y,qa.z,qa.w,qb.x,qb.y,qb.z,qb.w};
                #pragma unroll
                for (int mm=0;mm<CC;mm++) {
                    acc[mm].x += qm[mm]*cur[u].x;
                    acc[mm].y += qm[mm]*cur[u].y;
                    acc[mm].z += qm[mm]*cur[u].z;
                    acc[mm].w += qm[mm]*cur[u].w;
                }
            }
        }
        if (c0+4 < NOUT) {
            #pragma unroll
            for (int u=0;u<4;u++) cur[u]=nxt[u];
        }
    }
}

__global__ void __launch_bounds__(128) k_main(const float* __restrict__ queue,
                       const int* __restrict__ ids, const int* __restrict__ elem_ids,
                       float* __restrict__ out) {
    __shared__ float qv_sh[NOUT*8];   // [c][m] layout
    __shared__ int   n_sh[8];
    __shared__ int   e_sh[8];
    __shared__ float wsum[4*NOUT];
    int tid = threadIdx.x, lane = tid & 31, warp = tid >> 5;
    int j   = blockIdx.y;
    int s0  = blockIdx.x * 512;
    const float* Qb = queue + (long)j*NOUT*QS + s0 + tid*4;
    float* NQo = out + OFF_NQ + (long)j*NOUT*QS + s0 + tid*4;

    int4 myids = *(const int4*)(ids + (long)j*QS + s0 + tid*4);
    {
        float* dst = out + OFF_NIDS + (long)j*QS + s0 + tid*4;
        dst[0]=(float)myids.x; dst[1]=(float)myids.y;
        dst[2]=(float)myids.z; dst[3]=(float)myids.w;
    }
    for (int t=tid; t<4*NOUT; t+=128) wsum[t]=0.f;

    int off = g_grp_off[j];
    int cnt = g_grp_off[j+1]-off;
    int nch = (cnt+7)>>3; if (nch==0) nch=1;

    for (int ch=0; ch<nch; ch++) {
        int cc = cnt - ch*8; if (cc>8) cc=8; if (cc<0) cc=0;
        __syncthreads();
        for (int t=tid; t<NOUT*8; t+=128) {
            int m = t & 7;
            if (m < cc)
                qv_sh[t] = g_q[(long)g_grp_items[off+ch*8+m]*NOUT + (t>>3)];
        }
        if (tid < cc) {
            int n = g_grp_items[off+ch*8+tid];
            n_sh[tid]=n; e_sh[tid]=elem_ids[n];
        }
        __syncthreads();

        float4 acc[8];
        #pragma unroll
        for (int m=0;m<8;m++) acc[m]=make_float4(0.f,0.f,0.f,0.f);

        bool copy = (ch==0);
        #define DISP(CCV) case CCV: \
            if (copy) run_cols<CCV,true >(Qb,NQo,&wsum[warp*NOUT],qv_sh,lane,acc); \
            else      run_cols<CCV,false>(Qb,NQo,&wsum[warp*NOUT],qv_sh,lane,acc); break;
        switch (cc) {
            DISP(0) DISP(1) DISP(2) DISP(3) DISP(4) DISP(5) DISP(6) DISP(7) DISP(8)
        }
        #undef DISP

        for (int m=0;m<cc;m++) {
            int n = n_sh[m], e = e_sh[m];
            float* dst = out + OFF_LL + (long)n*(QS+1) + 1 + s0 + tid*4;
            dst[0] = (myids.x==e) ? (NEG_INF/TEMP) : acc[m].x/TEMP;
            dst[1] = (myids.y==e) ? (NEG_INF/TEMP) : acc[m].y/TEMP;
            dst[2] = (myids.z==e) ? (NEG_INF/TEMP) : acc[m].z/TEMP;
            dst[3] = (myids.w==e) ? (NEG_INF/TEMP) : acc[m].w/TEMP;
        }
    }
    __syncthreads();
    // per-s-quarter partial column sums: plain store into private slot (tid = c)
    {
        float s = wsum[tid] + wsum[NOUT+tid] + wsum[2*NOUT+tid] + wsum[3*NOUT+tid];
        g_negpart[((long)blockIdx.x*NQ + j)*NOUT + tid] = s;
    }
    // enqueue overwrite: this block exclusively owns (j, [s0, s0+512))
    for (int i=0;i<cnt;i++) {
        int n = g_grp_items[off+i];
        int col = g_cols[n];
        if (col >= s0 && col < s0+512) {
            out[OFF_NQ + (long)j*NOUT*QS + (long)tid*QS + col] = g_k[(long)n*NOUT+tid];
            if (tid==0) out[OFF_NIDS + (long)j*QS + col] = (float)elem_ids[n];
        }
    }
}

// 5) combine partials, transpose + scale the mean
__global__ void k_negmean() {
    int i = blockIdx.x*256+threadIdx.x;   // 32768
    int j = i >> 7, c = i & 127;
    long b = (long)NQ*NOUT;
    float s = g_negpart[(long)j*NOUT+c] + g_negpart[b+(long)j*NOUT+c]
            + g_negpart[2*b+(long)j*NOUT+c] + g_negpart[3*b+(long)j*NOUT+c];
    g_negmeanT[c*NQ + j] = s * (1.0f/2048.0f);
}

// 6) logits_global = q @ neg_global^T / TEMP  (64 blocks x 256)
__global__ void __launch_bounds__(256) k_global(float* __restrict__ out) {
    __shared__ float q_sh[16*128];
    int tid = threadIdx.x;
    int n0 = blockIdx.x*16;
    for (int t=tid; t<2048; t+=256) q_sh[t] = g_q[(long)n0*128 + t];
    __syncthreads();
    int jq = tid;
    float acc[16];
    #pragma unroll
    for (int m=0;m<16;m++) acc[m]=0.f;
    for (int c4=0;c4<128;c4+=4) {
        float w0 = g_negmeanT[(c4+0)*NQ+jq];
        float w1 = g_negmeanT[(c4+1)*NQ+jq];
        float w2 = g_negmeanT[(c4+2)*NQ+jq];
        float w3 = g_negmeanT[(c4+3)*NQ+jq];
        #pragma unroll
        for (int m=0;m<16;m++) {
            float4 x = *(const float4*)&q_sh[m*128+c4];
            acc[m] += x.x*w0+x.y*w1+x.z*w2+x.w*w3;
        }
    }
    #pragma unroll
    for (int m=0;m<16;m++)
        out[OFF_LG + (long)(n0+m)*NQ + jq] = acc[m]/TEMP;
}

extern "C" void kernel_launch(void* const* d_in, const int* in_sizes, int n_in,
                              void* d_out, int out_size) {
    (void)in_sizes; (void)n_in; (void)out_size;
    const float* inputs_q  = (const float*)d_in[0];
    const float* inputs_k  = (const float*)d_in[1];
    const int*   idx_q     = (const int*)d_in[2];
    const int*   idx_k     = (const int*)d_in[3];
    const int*   q_ids     = (const int*)d_in[4];
    const int*   elem_ids  = (const int*)d_in[5];
    const float* wq1 = (const float*)d_in[6];
    const float* bq1 = (const float*)d_in[7];
    const float* wq2 = (const float*)d_in[8];
    const float* bq2 = (const float*)d_in[9];
    const float* wk1 = (const float*)d_in[10];
    const float* bk1 = (const float*)d_in[11];
    const float* wk2 = (const float*)d_in[12];
    const float* bk2 = (const float*)d_in[13];
    const float* queue     = (const float*)d_in[14];
    const int*   ids       = (const int*)d_in[15];
    const int*   queue_ptr = (const int*)d_in[16];
    float* out = (float*)d_out;

    k_momentum<<<386,256>>>(wq1,bq1,wq2,bq2,wk1,bk1,wk2,bk2);
    k_proj2<<<128,256>>>(inputs_q, inputs_k, idx_q, idx_k, wq1,bq1,wq2,bq2);
    k_meta<<<1,1024>>>(q_ids, queue_ptr, out);
    dim3 gmain(4,256);
    k_main<<<gmain,128>>>(queue, ids, elem_ids, out);
    k_negmean<<<128,256>>>();
    k_global<<<64,256>>>(out);
}

// round 6
// speedup vs baseline: 2.1435x; 1.2344x over previous
#include <cuda_runtime.h>
#include <stdint.h>

#define N_NODES 4096
#define NEMB 256
#define NOUT 128
#define QS 2048
#define NQ 256
#define NN 1024
#define TEMP 0.07f
#define NEG_INF (-9.0e15f)
#define MMT 0.999f

// ---- output layout (flattened f32, reference tuple order) ----
#define OFF_LL   0L                                   // logits_local  [1024, 2049]
#define OFF_LABL (OFF_LL + (long)NN*(QS+1))           // labels_local  [1024]
#define OFF_LG   (OFF_LABL + NN)                      // logits_global [1024, 256]
#define OFF_LABG (OFF_LG + (long)NN*NQ)               // labels_global [1024]
#define OFF_NQ   (OFF_LABG + NN)                      // new_queue     [256,128,2048]
#define OFF_NIDS (OFF_NQ + (long)NQ*NOUT*QS)          // new_ids       [256,2048]
#define OFF_NPTR (OFF_NIDS + (long)NQ*QS)             // new_ptr       [256]

// ---- device scratch (every element fully overwritten every call) ----
__device__ float g_q[NN*NOUT];
__device__ float g_k[NN*NOUT];
__device__ float g_negpart[4*NQ*NOUT];   // per-s-quarter partial column sums
__device__ float g_negmeanT[NOUT*NQ];
__device__ int   g_cols[NN];
__device__ int   g_grp_off[NQ+1];
__device__ int   g_grp_items[NN];

// 1) merged q/k projection with momentum fused at the weight load.
//    blocks [0,128) -> q path, [128,256) -> k path; 8 rows per block.
__global__ void __launch_bounds__(256) k_proj2(
        const float* __restrict__ Xq, const float* __restrict__ Xk,
        const int* __restrict__ idxq, const int* __restrict__ idxk,
        const float* __restrict__ wq1, const float* __restrict__ bq1,
        const float* __restrict__ wq2, const float* __restrict__ bq2,
        const float* __restrict__ wk1, const float* __restrict__ bk1,
        const float* __restrict__ wk2, const float* __restrict__ bk2) {
    __shared__ float in_sh[8*256];
    __shared__ float h_sh [8*256];
    __shared__ float o_sh [8*128];
    __shared__ float nrm_sh[8];
    int mom = blockIdx.x >= 128;
    int blk = blockIdx.x & 127;
    const float* X   = mom ? Xk : Xq;
    const int*   idx = mom ? idxk : idxq;
    float* outQ = mom ? g_k : g_q;

    int tid = threadIdx.x;
    int n0  = blk * 8;
    for (int t = tid; t < 8*256; t += 256) {
        int r = t >> 8, c = t & 255;
        in_sh[t] = X[(long)idx[n0+r]*NEMB + c];
    }
    __syncthreads();
    { // layer 1: out col = tid, 8 rows
        float acc[8];
        #pragma unroll
        for (int m=0;m<8;m++) acc[m]=0.f;
        for (int c4=0;c4<256;c4+=4) {
            float w0,w1,w2,w3;
            if (mom) {
                w0 = wk1[(c4+0)*256+tid]*MMT + wq1[(c4+0)*256+tid]*(1.f-MMT);
                w1 = wk1[(c4+1)*256+tid]*MMT + wq1[(c4+1)*256+tid]*(1.f-MMT);
                w2 = wk1[(c4+2)*256+tid]*MMT + wq1[(c4+2)*256+tid]*(1.f-MMT);
                w3 = wk1[(c4+3)*256+tid]*MMT + wq1[(c4+3)*256+tid]*(1.f-MMT);
            } else {
                w0 = wq1[(c4+0)*256+tid];
                w1 = wq1[(c4+1)*256+tid];
                w2 = wq1[(c4+2)*256+tid];
                w3 = wq1[(c4+3)*256+tid];
            }
            #pragma unroll
            for (int m=0;m<8;m++) {
                float4 x = *(const float4*)&in_sh[m*256+c4];
                acc[m] += x.x*w0 + x.y*w1 + x.z*w2 + x.w*w3;
            }
        }
        float b = mom ? (bk1[tid]*MMT + bq1[tid]*(1.f-MMT)) : bq1[tid];
        #pragma unroll
        for (int m=0;m<8;m++) h_sh[m*256+tid] = fmaxf(acc[m]+b, 0.f);
    }
    __syncthreads();
    { // layer 2: out col = tid&127, rows (tid>>7)*4 ..+3
        int oc = tid & 127;
        int mb = (tid >> 7) * 4;
        float acc[4];
        #pragma unroll
        for (int m=0;m<4;m++) acc[m]=0.f;
        for (int c4=0;c4<256;c4+=4) {
            float w0,w1,w2,w3;
            if (mom) {
                w0 = wk2[(c4+0)*128+oc]*MMT + wq2[(c4+0)*128+oc]*(1.f-MMT);
                w1 = wk2[(c4+1)*128+oc]*MMT + wq2[(c4+1)*128+oc]*(1.f-MMT);
                w2 = wk2[(c4+2)*128+oc]*MMT + wq2[(c4+2)*128+oc]*(1.f-MMT);
                w3 = wk2[(c4+3)*128+oc]*MMT + wq2[(c4+3)*128+oc]*(1.f-MMT);
            } else {
                w0 = wq2[(c4+0)*128+oc];
                w1 = wq2[(c4+1)*128+oc];
                w2 = wq2[(c4+2)*128+oc];
                w3 = wq2[(c4+3)*128+oc];
            }
            #pragma unroll
            for (int m=0;m<4;m++) {
                float4 x = *(const float4*)&h_sh[(mb+m)*256+c4];
                acc[m] += x.x*w0 + x.y*w1 + x.z*w2 + x.w*w3;
            }
        }
        float b = mom ? (bk2[oc]*MMT + bq2[oc]*(1.f-MMT)) : bq2[oc];
        #pragma unroll
        for (int m=0;m<4;m++) o_sh[(mb+m)*128+oc] = acc[m]+b;
    }
    __syncthreads();
    if (tid < 8) {
        float ssq = 0.f;
        const float4* row = (const float4*)&o_sh[tid*128];
        #pragma unroll 8
        for (int i=0;i<32;i++) { float4 x=row[i]; ssq += x.x*x.x+x.y*x.y+x.z*x.z+x.w*x.w; }
        nrm_sh[tid] = 1.0f/sqrtf(ssq);
    }
    __syncthreads();
    for (int t=tid; t<8*128; t+=256) {
        int m = t>>7;
        outQ[(long)(n0+m)*NOUT + (t&127)] = o_sh[t]*nrm_sh[m];
    }
}

// 2) metadata: ranks/cols/counts (match_any), prefix-scan groups,
//    new_ptr, group item scatter.  1 block x 1024 threads.
__global__ void __launch_bounds__(1024) k_meta(const int* __restrict__ q_ids,
                                               const int* __restrict__ queue_ptr,
                                               float* __restrict__ out) {
    __shared__ int hist[32*NQ];   // 32 KB
    __shared__ int sc[NQ];
    __shared__ int excl[NQ];
    __shared__ int cnt_sh[NQ];
    int tid = threadIdx.x;
    int warp = tid >> 5, lane = tid & 31;
    for (int t=tid; t<32*NQ; t+=1024) hist[t]=0;
    __syncthreads();
    int qid = q_ids[tid];
    unsigned m = __match_any_sync(0xffffffffu, qid);
    int intra = __popc(m & ((1u<<lane)-1u));
    int leader = __ffs(m)-1;
    if (lane==leader) hist[warp*NQ + qid] = __popc(m);
    __syncthreads();
    int prior=0;
    #pragma unroll 4
    for (int w=0; w<warp; w++) prior += hist[w*NQ+qid];
    int rank = prior + intra;
    g_cols[tid] = (queue_ptr[qid] + rank) & (QS-1);
    if (tid < NQ) {
        int c=0;
        #pragma unroll 8
        for (int w=0;w<32;w++) c += hist[w*NQ+tid];
        cnt_sh[tid]=c;
        sc[tid]=c;
    }
    __syncthreads();
    for (int d=1; d<NQ; d<<=1) {
        int v = 0;
        if (tid < NQ && tid >= d) v = sc[tid-d];
        __syncthreads();
        if (tid < NQ) sc[tid] += v;
        __syncthreads();
    }
    if (tid < NQ) {
        int c = cnt_sh[tid];
        int e = sc[tid]-c;
        excl[tid] = e;
        g_grp_off[tid] = e;
        if (tid==NQ-1) g_grp_off[NQ] = sc[NQ-1];
        out[OFF_NPTR + tid] = (float)((queue_ptr[tid]+c) & (QS-1));
    }
    __syncthreads();
    g_grp_items[excl[qid] + rank] = tid;
}

// 3) fused streaming pass.  grid (4, 256) x 256 threads; block owns the
//    s-slice [s0, s0+512) of queue id j; each thread owns a float2.
template<int CC, bool COPY>
__device__ __forceinline__ void run_cols2(
        const float* __restrict__ Qb, float* __restrict__ NQo,
        float* __restrict__ wsumW, const float* __restrict__ qv_sh,
        int lane, float2* acc) {
    float2 cur[4];
    #pragma unroll
    for (int u=0;u<4;u++) cur[u] = __ldcs((const float2*)(Qb + (long)u*QS));
    #pragma unroll
    for (int c0=0;c0<NOUT;c0+=4) {
        float2 nxt[4];
        if (c0+4 < NOUT) {
            #pragma unroll
            for (int u=0;u<4;u++)
                nxt[u] = __ldcs((const float2*)(Qb + (long)(c0+4+u)*QS));
        }
        if (COPY) {
            float p[4];
            #pragma unroll
            for (int u=0;u<4;u++) {
                __stcs((float2*)(NQo + (long)(c0+u)*QS), cur[u]);
                p[u] = cur[u].x + cur[u].y;
            }
            #pragma unroll
            for (int o=16;o;o>>=1) {
                #pragma unroll
                for (int u=0;u<4;u++) p[u] += __shfl_xor_sync(0xffffffffu, p[u], o);
            }
            if (lane==0) {
                #pragma unroll
                for (int u=0;u<4;u++) wsumW[c0+u] += p[u];
            }
        }
        if (CC > 0) {
            #pragma unroll
            for (int u=0;u<4;u++) {
                const float* qp = qv_sh + (c0+u)*8;
                #pragma unroll
                for (int mm=0;mm<CC;mm++) {
                    float qm = qp[mm];
                    acc[mm].x += qm*cur[u].x;
                    acc[mm].y += qm*cur[u].y;
                }
            }
        }
        if (c0+4 < NOUT) {
            #pragma unroll
            for (int u=0;u<4;u++) cur[u]=nxt[u];
        }
    }
}

__global__ void __launch_bounds__(256,4) k_main(const float* __restrict__ queue,
                       const int* __restrict__ ids, const int* __restrict__ elem_ids,
                       float* __restrict__ out) {
    __shared__ float qv_sh[NOUT*8];   // [c][m] layout
    __shared__ int   n_sh[8];
    __shared__ int   e_sh[8];
    __shared__ float wsum[8*NOUT];
    int tid = threadIdx.x, lane = tid & 31, warp = tid >> 5;
    int j   = blockIdx.y;
    int s0  = blockIdx.x * 512;
    const float* Qb = queue + (long)j*NOUT*QS + s0 + tid*2;
    float* NQo = out + OFF_NQ + (long)j*NOUT*QS + s0 + tid*2;

    int2 myids = *(const int2*)(ids + (long)j*QS + s0 + tid*2);
    {
        float* dst = out + OFF_NIDS + (long)j*QS + s0 + tid*2;
        dst[0]=(float)myids.x; dst[1]=(float)myids.y;
    }
    for (int t=tid; t<8*NOUT; t+=256) wsum[t]=0.f;

    int off = g_grp_off[j];
    int cnt = g_grp_off[j+1]-off;
    int nch = (cnt+7)>>3; if (nch==0) nch=1;

    for (int ch=0; ch<nch; ch++) {
        int cc = cnt - ch*8; if (cc>8) cc=8; if (cc<0) cc=0;
        __syncthreads();
        for (int t=tid; t<NOUT*8; t+=256) {
            int m = t & 7;
            if (m < cc)
                qv_sh[t] = g_q[(long)g_grp_items[off+ch*8+m]*NOUT + (t>>3)];
        }
        if (tid < cc) {
            int n = g_grp_items[off+ch*8+tid];
            n_sh[tid]=n; e_sh[tid]=elem_ids[n];
        }
        __syncthreads();

        float2 acc[8];
        #pragma unroll
        for (int m=0;m<8;m++) acc[m]=make_float2(0.f,0.f);

        bool copy = (ch==0);
        #define DISP(CCV) case CCV: \
            if (copy) run_cols2<CCV,true >(Qb,NQo,&wsum[warp*NOUT],qv_sh,lane,acc); \
            else      run_cols2<CCV,false>(Qb,NQo,&wsum[warp*NOUT],qv_sh,lane,acc); break;
        switch (cc) {
            DISP(0) DISP(1) DISP(2) DISP(3) DISP(4) DISP(5) DISP(6) DISP(7) DISP(8)
        }
        #undef DISP

        for (int m=0;m<cc;m++) {
            int n = n_sh[m], e = e_sh[m];
            float* dst = out + OFF_LL + (long)n*(QS+1) + 1 + s0 + tid*2;
            dst[0] = (myids.x==e) ? (NEG_INF/TEMP) : acc[m].x/TEMP;
            dst[1] = (myids.y==e) ? (NEG_INF/TEMP) : acc[m].y/TEMP;
        }
    }
    __syncthreads();
    // per-s-quarter partial column sums: plain store (tid = c)
    if (tid < NOUT) {
        float s = 0.f;
        #pragma unroll
        for (int w=0;w<8;w++) s += wsum[w*NOUT+tid];
        g_negpart[((long)blockIdx.x*NQ + j)*NOUT + tid] = s;
    }
    // enqueue overwrite: this block exclusively owns (j, [s0, s0+512))
    if (tid < NOUT) {
        for (int i=0;i<cnt;i++) {
            int n = g_grp_items[off+i];
            int col = g_cols[n];
            if (col >= s0 && col < s0+512) {
                out[OFF_NQ + (long)j*NOUT*QS + (long)tid*QS + col] = g_k[(long)n*NOUT+tid];
                if (tid==0) out[OFF_NIDS + (long)j*QS + col] = (float)elem_ids[n];
            }
        }
    }
}

// 4) combine partials, transpose + scale the mean
__global__ void k_negmean() {
    int i = blockIdx.x*256+threadIdx.x;   // 32768
    int j = i >> 7, c = i & 127;
    long b = (long)NQ*NOUT;
    float s = g_negpart[(long)j*NOUT+c] + g_negpart[b+(long)j*NOUT+c]
            + g_negpart[2*b+(long)j*NOUT+c] + g_negpart[3*b+(long)j*NOUT+c];
    g_negmeanT[c*NQ + j] = s * (1.0f/2048.0f);
}

// 5) logits_global + l_pos + labels  (64 blocks x 256)
__global__ void __launch_bounds__(256) k_global(const int* __restrict__ q_ids,
                                                float* __restrict__ out) {
    __shared__ float q_sh[16*128];
    int tid = threadIdx.x, lane = tid & 31, warp = tid >> 5;
    int n0 = blockIdx.x*16;
    for (int t=tid; t<2048; t+=256) q_sh[t] = g_q[(long)n0*128 + t];
    __syncthreads();
    // l_pos + labels: warp w -> rows n0+2w, n0+2w+1
    #pragma unroll
    for (int r=0;r<2;r++) {
        int n = n0 + warp*2 + r;
        float4 a = *(const float4*)&q_sh[(warp*2+r)*128 + lane*4];
        float4 b = *(const float4*)(g_k + (long)n*NOUT + lane*4);
        float d = a.x*b.x + a.y*b.y + a.z*b.z + a.w*b.w;
        #pragma unroll
        for (int o=16;o;o>>=1) d += __shfl_xor_sync(0xffffffffu, d, o);
        if (lane==0) {
            out[OFF_LL + (long)n*(QS+1)] = d / TEMP;
            out[OFF_LABL + n] = 0.f;
            out[OFF_LABG + n] = (float)q_ids[n];
        }
    }
    // logits_global
    int jq = tid;
    float acc[16];
    #pragma unroll
    for (int m=0;m<16;m++) acc[m]=0.f;
    for (int c4=0;c4<128;c4+=4) {
        float w0 = g_negmeanT[(c4+0)*NQ+jq];
        float w1 = g_negmeanT[(c4+1)*NQ+jq];
        float w2 = g_negmeanT[(c4+2)*NQ+jq];
        float w3 = g_negmeanT[(c4+3)*NQ+jq];
        #pragma unroll
        for (int m=0;m<16;m++) {
            float4 x = *(const float4*)&q_sh[m*128+c4];
            acc[m] += x.x*w0+x.y*w1+x.z*w2+x.w*w3;
        }
    }
    #pragma unroll
    for (int m=0;m<16;m++)
        out[OFF_LG + (long)(n0+m)*NQ + jq] = acc[m]/TEMP;
}

extern "C" void kernel_launch(void* const* d_in, const int* in_sizes, int n_in,
                              void* d_out, int out_size) {
    (void)in_sizes; (void)n_in; (void)out_size;
    const float* inputs_q  = (const float*)d_in[0];
    const float* inputs_k  = (const float*)d_in[1];
    const int*   idx_q     = (const int*)d_in[2];
    const int*   idx_k     = (const int*)d_in[3];
    const int*   q_ids     = (const int*)d_in[4];
    const int*   elem_ids  = (const int*)d_in[5];
    const float* wq1 = (const float*)d_in[6];
    const float* bq1 = (const float*)d_in[7];
    const float* wq2 = (const float*)d_in[8];
    const float* bq2 = (const float*)d_in[9];
    const float* wk1 = (const float*)d_in[10];
    const float* bk1 = (const float*)d_in[11];
    const float* wk2 = (const float*)d_in[12];
    const float* bk2 = (const float*)d_in[13];
    const float* queue     = (const float*)d_in[14];
    const int*   ids       = (const int*)d_in[15];
    const int*   queue_ptr = (const int*)d_in[16];
    float* out = (float*)d_out;

    k_proj2<<<256,256>>>(inputs_q, inputs_k, idx_q, idx_k,
                         wq1,bq1,wq2,bq2, wk1,bk1,wk2,bk2);
    k_meta<<<1,1024>>>(q_ids, queue_ptr, out);
    dim3 gmain(4,256);
    k_main<<<gmain,256>>>(queue, ids, elem_ids, out);
    k_negmean<<<128,256>>>();
    k_global<<<64,256>>>(q_ids, out);
}